// round 1
// baseline (speedup 1.0000x reference)
#include <cuda_runtime.h>
#include <math.h>

#define NB 64
#define MB 32
#define NM (NB*MB)      // 2048 node rows
#define FEATD 256
#define POSD 6
#define DD 262
#define MSGD 128
#define NCLSD 7

// ---------------- scratch (static device memory; no allocation) ----------------
__device__ float g_nf [NM*DD];
__device__ float g_h  [NM*DD];
__device__ float g_A  [NM*DD];
__device__ float g_B  [NM*DD];
__device__ float g_att[NB*MB*MB];
__device__ float g_msg[NM*MSGD];
__device__ float g_mv [NM*MSGD];
__device__ float g_gx [NM*3*DD];
__device__ float g_gh [NM*3*DD];
__device__ float g_t  [NM*MSGD];

__device__ __forceinline__ float sigmoidf(float x) {
    return 1.0f / (1.0f + expf(-x));
}

// ---------------- build nf = [feat, pos], h = nf ----------------
__global__ void build_nf_kernel(const float* __restrict__ feat,
                                const float* __restrict__ pos) {
    int idx = blockIdx.x * blockDim.x + threadIdx.x;
    if (idx >= NM * DD) return;
    int row = idx / DD, c = idx % DD;
    float v = (c < FEATD) ? feat[row * FEATD + c] : pos[row * POSD + (c - FEATD)];
    g_nf[idx] = v;
    g_h[idx]  = v;
}

// ---------------- generic C = A * W^T (+bias)(+relu) ----------------
// A: M x K (lda), W: N x K (ldw, row-major), C: M x N (ldc)
#define TS 64
#define KS 16
__global__ void gemm_nt_kernel(const float* __restrict__ A, int lda,
                               const float* __restrict__ W, int ldw,
                               const float* __restrict__ bias,
                               float* __restrict__ C, int ldc,
                               int M, int N, int K, int relu_flag) {
    __shared__ float As[KS][TS + 1];
    __shared__ float Ws[KS][TS + 1];
    int tx = threadIdx.x;             // 0..15
    int ty = threadIdx.y;             // 0..15
    int tid = ty * 16 + tx;
    int m0 = blockIdx.y * TS, n0 = blockIdx.x * TS;

    float acc[4][4] = {};
    for (int k0 = 0; k0 < K; k0 += KS) {
        #pragma unroll
        for (int i = tid; i < TS * KS; i += 256) {
            int mm = i / KS, kk = i % KS;
            int m = m0 + mm, k = k0 + kk;
            As[kk][mm] = (m < M && k < K) ? A[(size_t)m * lda + k] : 0.0f;
        }
        #pragma unroll
        for (int i = tid; i < TS * KS; i += 256) {
            int nn = i / KS, kk = i % KS;
            int n = n0 + nn, k = k0 + kk;
            Ws[kk][nn] = (n < N && k < K) ? W[(size_t)n * ldw + k] : 0.0f;
        }
        __syncthreads();
        #pragma unroll
        for (int kk = 0; kk < KS; kk++) {
            float a[4], w[4];
            #pragma unroll
            for (int i = 0; i < 4; i++) a[i] = As[kk][ty * 4 + i];
            #pragma unroll
            for (int j = 0; j < 4; j++) w[j] = Ws[kk][tx * 4 + j];
            #pragma unroll
            for (int i = 0; i < 4; i++)
                #pragma unroll
                for (int j = 0; j < 4; j++)
                    acc[i][j] += a[i] * w[j];
        }
        __syncthreads();
    }
    #pragma unroll
    for (int i = 0; i < 4; i++) {
        int m = m0 + ty * 4 + i;
        if (m >= M) continue;
        #pragma unroll
        for (int j = 0; j < 4; j++) {
            int n = n0 + tx * 4 + j;
            if (n >= N) continue;
            float v = acc[i][j] + (bias ? bias[n] : 0.0f);
            if (relu_flag) v = fmaxf(v, 0.0f);
            C[(size_t)m * ldc + n] = v;
        }
    }
}

// ---------------- attention: one warp per (b, n, w) pair ----------------
// att[b,n,w] = sigmoid(b2 + sum_d w2[d] * relu((valid ? A[b,n,d]+B[b,w,d] : 0) + b1[d]))
__global__ void att_kernel(const float* __restrict__ b1,
                           const float* __restrict__ w2,
                           const float* __restrict__ b2v,
                           const int* __restrict__ num_rec,
                           float* __restrict__ att_out) {
    int gwarp = (blockIdx.x * blockDim.x + threadIdx.x) >> 5;
    int lane = threadIdx.x & 31;
    if (gwarp >= NB * MB * MB) return;
    int b = gwarp >> 10;
    int rem = gwarp & 1023;
    int n = rem >> 5, w = rem & 31;
    int nr = num_rec[b];
    bool valid = (n < nr) && (w < nr);

    const float* Ar = g_A + (size_t)(b * MB + n) * DD;
    const float* Br = g_B + (size_t)(b * MB + w) * DD;
    float s = 0.0f;
    for (int d = lane; d < DD; d += 32) {
        float v = valid ? (Ar[d] + Br[d]) : 0.0f;
        v = fmaxf(v + b1[d], 0.0f);
        s += v * w2[d];
    }
    #pragma unroll
    for (int o = 16; o > 0; o >>= 1) s += __shfl_xor_sync(0xffffffffu, s, o);
    if (lane == 0) {
        float a = sigmoidf(s + b2v[0]);
        g_att[gwarp] = a;
        att_out[gwarp] = a;
    }
}

// ---------------- mv[b,n,k] = sum_{w < nr_b} att[b,n,w] * msg[b,w,k] ----------------
__global__ void mv_kernel(const int* __restrict__ num_rec) {
    int bn = blockIdx.x;              // 0..2047
    int b = bn >> 5;
    int k = threadIdx.x;              // 0..127
    int nr = num_rec[b];
    const float* arow = g_att + (size_t)bn * MB;
    const float* mb = g_msg + (size_t)b * MB * MSGD;
    float s = 0.0f;
    for (int w = 0; w < nr; w++) s += arow[w] * mb[w * MSGD + k];
    g_mv[(size_t)bn * MSGD + k] = s;
}

// ---------------- GRU combine (in-place h update, vmask) ----------------
__global__ void gru_kernel(const int* __restrict__ num_rec) {
    int idx = blockIdx.x * blockDim.x + threadIdx.x;
    if (idx >= NM * DD) return;
    int row = idx / DD, d = idx % DD;
    int b = row >> 5, m = row & 31;
    size_t base = (size_t)row * (3 * DD);
    float xr = g_gx[base + d];
    float xz = g_gx[base + DD + d];
    float xn = g_gx[base + 2 * DD + d];
    float hr = g_gh[base + d];
    float hz = g_gh[base + DD + d];
    float hn = g_gh[base + 2 * DD + d];
    float r = sigmoidf(xr + hr);
    float z = sigmoidf(xz + hz);
    float c = tanhf(xn + r * hn);
    float hv = g_h[idx];
    float out = (1.0f - z) * c + z * hv;
    g_h[idx] = (m < num_rec[b]) ? out : 0.0f;
}

// ---------------- readout second layer: pred = t @ ro_w2^T + ro_b2, vmask ----------------
__global__ void pred_kernel(const float* __restrict__ w2,
                            const float* __restrict__ b2,
                            const int* __restrict__ num_rec,
                            float* __restrict__ out) {
    int idx = blockIdx.x * blockDim.x + threadIdx.x;
    if (idx >= NM * NCLSD) return;
    int row = idx / NCLSD, c = idx % NCLSD;
    int b = row >> 5, m = row & 31;
    const float* tr = g_t + (size_t)row * MSGD;
    const float* wr = w2 + (size_t)c * MSGD;
    float s = b2[c];
    #pragma unroll 4
    for (int k = 0; k < MSGD; k++) s += tr[k] * wr[k];
    out[idx] = (m < num_rec[b]) ? s : 0.0f;
}

// ---------------- host launcher ----------------
static void launch_gemm(const float* A, int lda, const float* W, int ldw,
                        const float* bias, float* C, int ldc,
                        int M, int N, int K, int relu_flag) {
    dim3 grid((N + TS - 1) / TS, (M + TS - 1) / TS);
    dim3 block(16, 16);
    gemm_nt_kernel<<<grid, block>>>(A, lda, W, ldw, bias, C, ldc, M, N, K, relu_flag);
}

extern "C" void kernel_launch(void* const* d_in, const int* in_sizes, int n_in,
                              void* d_out, int out_size) {
    const float* feat    = (const float*)d_in[0];
    const float* pos     = (const float*)d_in[1];
    const int*   num_rec = (const int*)  d_in[2];
    const float* link_w1 = (const float*)d_in[3];
    const float* link_b1 = (const float*)d_in[4];
    const float* link_w2 = (const float*)d_in[5];
    const float* link_b2 = (const float*)d_in[6];
    const float* msg_w   = (const float*)d_in[7];
    const float* msg_b   = (const float*)d_in[8];
    const float* gru_w_ih= (const float*)d_in[9];
    const float* gru_w_hh= (const float*)d_in[10];
    const float* gru_b_ih= (const float*)d_in[11];
    const float* gru_b_hh= (const float*)d_in[12];
    const float* ro_w1   = (const float*)d_in[13];
    const float* ro_b1   = (const float*)d_in[14];
    const float* ro_w2   = (const float*)d_in[15];
    const float* ro_b2   = (const float*)d_in[16];
    float* out = (float*)d_out;           // [pred (64*32*7) | attmat (64*32*32)]

    // resolve device-global scratch addresses
    float *p_nf, *p_h, *p_A, *p_B, *p_msg, *p_mv, *p_gx, *p_gh, *p_t;
    cudaGetSymbolAddress((void**)&p_nf,  g_nf);
    cudaGetSymbolAddress((void**)&p_h,   g_h);
    cudaGetSymbolAddress((void**)&p_A,   g_A);
    cudaGetSymbolAddress((void**)&p_B,   g_B);
    cudaGetSymbolAddress((void**)&p_msg, g_msg);
    cudaGetSymbolAddress((void**)&p_mv,  g_mv);
    cudaGetSymbolAddress((void**)&p_gx,  g_gx);
    cudaGetSymbolAddress((void**)&p_gh,  g_gh);
    cudaGetSymbolAddress((void**)&p_t,   g_t);

    // 1) nf = [feat, pos]; h = nf
    {
        int total = NM * DD;
        build_nf_kernel<<<(total + 255) / 256, 256>>>(feat, pos);
    }

    // 2) low-rank edge MLP: A = nf @ W1a^T, B = nf @ W1b^T  (W1 is 262 x 524 row-major)
    launch_gemm(p_nf, DD, link_w1,        2 * DD, nullptr, p_A, DD, NM, DD, DD, 0);
    launch_gemm(p_nf, DD, link_w1 + DD,   2 * DD, nullptr, p_B, DD, NM, DD, DD, 0);

    // 3) attention per pair (writes scratch and output attmat region)
    {
        int warps = NB * MB * MB;             // 65536
        int threads = warps * 32;
        att_kernel<<<(threads + 255) / 256, 256>>>(link_b1, link_w2, link_b2,
                                                   num_rec, out + NM * NCLSD);
    }

    // 4) two message-passing GRU rounds
    for (int round = 0; round < 2; round++) {
        launch_gemm(p_h,  DD,   msg_w,    DD,   msg_b,    p_msg, MSGD,  NM, MSGD,  DD,   0);
        mv_kernel<<<NM, MSGD>>>(num_rec);
        launch_gemm(p_mv, MSGD, gru_w_ih, MSGD, gru_b_ih, p_gx,  3*DD,  NM, 3*DD,  MSGD, 0);
        launch_gemm(p_h,  DD,   gru_w_hh, DD,   gru_b_hh, p_gh,  3*DD,  NM, 3*DD,  DD,   0);
        {
            int total = NM * DD;
            gru_kernel<<<(total + 255) / 256, 256>>>(num_rec);
        }
    }

    // 5) readout
    launch_gemm(p_h, DD, ro_w1, DD, ro_b1, p_t, MSGD, NM, MSGD, DD, 1);
    {
        int total = NM * NCLSD;
        pred_kernel<<<(total + 127) / 128, 128>>>(ro_w2, ro_b2, num_rec, out);
    }
    (void)in_sizes; (void)n_in; (void)out_size;
}